// round 1
// baseline (speedup 1.0000x reference)
#include <cuda_runtime.h>
#include <cstdint>

// Problem constants (fixed by the dataset shapes)
#define B_DIM 32
#define IN_PLANES 128
#define PLANES 32
#define PITCH 132   // 128 + 4 pad; pitch mod 32 == 4 with odd (pitch/4) -> conflict-free wsT reads

// packed f32x2 FMA: lo += x.lo*w.lo ; hi += x.hi*w.hi   (full fp32 precision, 2x FFMA rate)
#define FMA2(a, xx, ww) asm("fma.rn.f32x2 %0, %1, %2, %0;" : "+l"(a) : "l"(xx), "l"(ww))

static __device__ __forceinline__ unsigned long long dal(double d) {
    return __double_as_longlong(d);
}

__global__ __launch_bounds__(64) void voxel_mlp_kernel(
    const float* __restrict__ x,        // [B, n_sel, 128]
    const int*   __restrict__ vidx,     // [n_sel]
    const float* __restrict__ w0,       // [n_vox, 128, 32]
    const float* __restrict__ b0,       // [n_vox, 32]
    const float* __restrict__ w1,       // [n_vox, 32] (last dim 1)
    const float* __restrict__ b1,       // [n_vox]
    float*       __restrict__ out,      // [B, n_sel]
    int n_sel)
{
    __shared__ float xs[B_DIM * PITCH];    // xs[b][k]
    __shared__ float wsT[PLANES * PITCH];  // wsT[o][k]  (transposed w0)

    const int n = blockIdx.x;
    const int t = threadIdx.x;
    const int v = vidx[n];

    const float* xg = x  + (size_t)n * IN_PLANES;
    const float* wg = w0 + (size_t)v * (IN_PLANES * PLANES);

    // ---- load x: 32 rows of 128 floats (32 float4 each), coalesced, direct copy ----
    #pragma unroll
    for (int j = t; j < B_DIM * (IN_PLANES / 4); j += 64) {
        int b  = j >> 5;        // 0..31
        int c4 = j & 31;        // float4 index within row
        float4 val = *reinterpret_cast<const float4*>(xg + (size_t)b * n_sel * IN_PLANES + c4 * 4);
        *reinterpret_cast<float4*>(&xs[b * PITCH + c4 * 4]) = val;
    }

    // ---- load w0 [128][32], store transposed into wsT[o][k] ----
    #pragma unroll
    for (int j = t; j < IN_PLANES * (PLANES / 4); j += 64) {
        int k  = j >> 3;        // 0..127
        int o4 = j & 7;         // float4 index within the 32-wide row
        float4 val = *reinterpret_cast<const float4*>(wg + k * PLANES + o4 * 4);
        wsT[(o4 * 4 + 0) * PITCH + k] = val.x;
        wsT[(o4 * 4 + 1) * PITCH + k] = val.y;
        wsT[(o4 * 4 + 2) * PITCH + k] = val.z;
        wsT[(o4 * 4 + 3) * PITCH + k] = val.w;
    }
    __syncthreads();

    // thread tile: b in {4r..4r+3}, o in {c, c+8, c+16, c+24}
    const int r = t >> 3;   // 0..7
    const int c = t & 7;    // 0..7

    unsigned long long acc[4][4];
    #pragma unroll
    for (int i = 0; i < 4; i++)
        #pragma unroll
        for (int jo = 0; jo < 4; jo++)
            acc[i][jo] = 0ULL;   // {0.0f, 0.0f}

    // ---- main GEMM: pairs packed along k ----
    #pragma unroll
    for (int k = 0; k < IN_PLANES; k += 4) {
        unsigned long long xk0[4], xk1[4], wk0[4], wk1[4];
        #pragma unroll
        for (int i = 0; i < 4; i++) {
            double2 d = *reinterpret_cast<const double2*>(&xs[(4 * r + i) * PITCH + k]);
            xk0[i] = dal(d.x);  // {x[k],   x[k+1]}
            xk1[i] = dal(d.y);  // {x[k+2], x[k+3]}
        }
        #pragma unroll
        for (int jo = 0; jo < 4; jo++) {
            double2 d = *reinterpret_cast<const double2*>(&wsT[(c + 8 * jo) * PITCH + k]);
            wk0[jo] = dal(d.x);
            wk1[jo] = dal(d.y);
        }
        #pragma unroll
        for (int i = 0; i < 4; i++)
            #pragma unroll
            for (int jo = 0; jo < 4; jo++) {
                FMA2(acc[i][jo], xk0[i], wk0[jo]);
                FMA2(acc[i][jo], xk1[i], wk1[jo]);
            }
    }

    // ---- epilogue: /128 + b0, exact-erf GELU, dot with w1, /32 + b1 ----
    const float inv_in = 1.0f / (float)IN_PLANES;
    const float inv_p  = 1.0f / (float)PLANES;

    float b0v[4], w1v[4];
    #pragma unroll
    for (int jo = 0; jo < 4; jo++) {
        int o = c + 8 * jo;
        b0v[jo] = b0[(size_t)v * PLANES + o];
        w1v[jo] = w1[(size_t)v * PLANES + o];
    }
    const float b1v = b1[v];

    float s[4];
    #pragma unroll
    for (int i = 0; i < 4; i++) {
        s[i] = 0.0f;
        #pragma unroll
        for (int jo = 0; jo < 4; jo++) {
            unsigned long long a = acc[i][jo];
            float lo = __uint_as_float((unsigned)(a & 0xffffffffULL));
            float hi = __uint_as_float((unsigned)(a >> 32));
            float h  = (lo + hi) * inv_in + b0v[jo];
            float g  = h * normcdff(h);          // exact-erf GELU
            s[i] += g * w1v[jo];
        }
    }

    // reduce across the 8 c-lanes (groups of 8 lanes share r)
    #pragma unroll
    for (int i = 0; i < 4; i++) {
        s[i] += __shfl_xor_sync(0xffffffffu, s[i], 1);
        s[i] += __shfl_xor_sync(0xffffffffu, s[i], 2);
        s[i] += __shfl_xor_sync(0xffffffffu, s[i], 4);
    }

    if (c == 0) {
        #pragma unroll
        for (int i = 0; i < 4; i++) {
            int b = 4 * r + i;
            out[(size_t)b * n_sel + n] = s[i] * inv_p + b1v;
        }
    }
}

extern "C" void kernel_launch(void* const* d_in, const int* in_sizes, int n_in,
                              void* d_out, int out_size) {
    const float* x    = (const float*)d_in[0];
    const int*   vidx = (const int*)  d_in[1];
    const float* w0   = (const float*)d_in[2];
    const float* b0   = (const float*)d_in[3];
    const float* w1   = (const float*)d_in[4];
    const float* b1   = (const float*)d_in[5];
    float*       out  = (float*)d_out;

    const int n_sel = in_sizes[1];
    voxel_mlp_kernel<<<n_sel, 64>>>(x, vidx, w0, b0, w1, b1, out, n_sel);
}